// round 4
// baseline (speedup 1.0000x reference)
#include <cuda_runtime.h>
#include <cuda_bf16.h>

// MultiHeadSpMM: out[r, h*D+d] = sum_{e: row[e]==r} attention[e,h] * h[col[e],h,d]
// N=100000, E=1600000, H=4, D=8 (H*D == 32 == warpSize). row[] is sorted.
//
// Strategy:
//   Kernel A: build CSR row_ptr from sorted row[] into __device__ scratch.
//   Kernel B: one warp per output row; lane l = h*8+d. Each edge costs one
//             coalesced 128B gather of h[col[e]] + broadcast att loads.
//             No atomics; every output element written exactly once.

#define MAX_NODES (1 << 21)  // scratch capacity for row_ptr (N+1 <= this)

__device__ int g_row_ptr[MAX_NODES + 1];

__global__ void build_row_ptr_kernel(const int* __restrict__ row, int E, int N) {
    int e = blockIdx.x * blockDim.x + threadIdx.x;
    if (e >= E) return;
    int r = row[e];
    if (r < 0) r = 0;
    if (r >= N) r = N - 1;
    int prev;
    if (e == 0) {
        prev = -1;
    } else {
        prev = row[e - 1];
        if (prev < 0) prev = 0;
        if (prev >= N) prev = N - 1;
    }
    // Fill start offsets for row r and any empty rows before it.
    for (int i = prev + 1; i <= r; ++i) g_row_ptr[i] = e;
    if (e == E - 1) {
        for (int i = r + 1; i <= N; ++i) g_row_ptr[i] = E;
    }
}

__global__ __launch_bounds__(256) void spmm_warp_per_row_kernel(
    const int* __restrict__ col,
    const float* __restrict__ att,   // (E, 4)
    const float* __restrict__ hfeat, // (N, 32)
    float* __restrict__ out,         // (N, 32)
    int N)
{
    int warp = (blockIdx.x * blockDim.x + threadIdx.x) >> 5;
    int lane = threadIdx.x & 31;
    if (warp >= N) return;

    int beg = g_row_ptr[warp];
    int end = g_row_ptr[warp + 1];

    const int head = lane >> 3;  // 0..3
    const int nmax = N - 1;

    float acc = 0.0f;
    int e = beg;

    // 4-edge unroll: 4 independent 128B gathers in flight per warp.
    for (; e + 3 < end; e += 4) {
        int c0 = __ldg(&col[e]);
        int c1 = __ldg(&col[e + 1]);
        int c2 = __ldg(&col[e + 2]);
        int c3 = __ldg(&col[e + 3]);
        c0 = min(max(c0, 0), nmax);
        c1 = min(max(c1, 0), nmax);
        c2 = min(max(c2, 0), nmax);
        c3 = min(max(c3, 0), nmax);
        float a0 = __ldg(&att[(e    ) * 4 + head]);
        float a1 = __ldg(&att[(e + 1) * 4 + head]);
        float a2 = __ldg(&att[(e + 2) * 4 + head]);
        float a3 = __ldg(&att[(e + 3) * 4 + head]);
        float v0 = __ldg(&hfeat[c0 * 32 + lane]);
        float v1 = __ldg(&hfeat[c1 * 32 + lane]);
        float v2 = __ldg(&hfeat[c2 * 32 + lane]);
        float v3 = __ldg(&hfeat[c3 * 32 + lane]);
        acc = fmaf(a0, v0, acc);
        acc = fmaf(a1, v1, acc);
        acc = fmaf(a2, v2, acc);
        acc = fmaf(a3, v3, acc);
    }
    for (; e < end; ++e) {
        int c0 = __ldg(&col[e]);
        c0 = min(max(c0, 0), nmax);
        float a0 = __ldg(&att[e * 4 + head]);
        acc = fmaf(a0, __ldg(&hfeat[c0 * 32 + lane]), acc);
    }

    out[warp * 32 + lane] = acc;  // empty rows write 0 (out is poisoned)
}

extern "C" void kernel_launch(void* const* d_in, const int* in_sizes, int n_in,
                              void* d_out, int out_size) {
    const int*   row  = (const int*)  d_in[0];
    const int*   col  = (const int*)  d_in[1];
    const float* att  = (const float*)d_in[2];
    const float* hft  = (const float*)d_in[3];
    float*       out  = (float*)      d_out;

    int E = in_sizes[0];
    int N = in_sizes[3] / 32;  // h is (N, 4, 8)

    {
        int threads = 256;
        int blocks = (E + threads - 1) / threads;
        build_row_ptr_kernel<<<blocks, threads>>>(row, E, N);
    }
    {
        int threads = 256;                      // 8 warps per block
        int warps_needed = N;
        int blocks = (warps_needed * 32 + threads - 1) / threads;
        spmm_warp_per_row_kernel<<<blocks, threads>>>(col, att, hft, out, N);
    }
}

// round 5
// speedup vs baseline: 1.1763x; 1.1763x over previous
#include <cuda_runtime.h>
#include <cuda_bf16.h>

// MultiHeadSpMM: out[r, h*D+d] = sum_{e: row[e]==r} attention[e,h] * h[col[e],h,d]
// N=100000, E=1600000, H=4, D=8 (H*D == 32). row[] is sorted.
//
// R5: LDG-instruction-count optimized (R4 was LSU-issue bound: 3 LDG/edge).
//   One warp per row. Lane decomposition: group g = lane>>3 owns edge base+g,
//   quarter q = lane&7 owns features [4q, 4q+4) as a float4.
//   Per 4 edges: 1 LDG.128 (hfeat) + 1 LDG.32 (col) + 1 LDG.32 (att).
//   Tail edges predicated (att=0). Final 2-step shfl-xor group reduction,
//   lanes 0..7 store one STG.128 each. Empty rows write zeros.

#define MAX_NODES (1 << 21)

__device__ int g_row_ptr[MAX_NODES + 1];

__global__ void build_row_ptr_kernel(const int* __restrict__ row, int E, int N) {
    int e = blockIdx.x * blockDim.x + threadIdx.x;
    if (e >= E) return;
    int r = row[e];
    if (r < 0) r = 0;
    if (r >= N) r = N - 1;
    int prev;
    if (e == 0) {
        prev = -1;
    } else {
        prev = row[e - 1];
        if (prev < 0) prev = 0;
        if (prev >= N) prev = N - 1;
    }
    for (int i = prev + 1; i <= r; ++i) g_row_ptr[i] = e;
    if (e == E - 1) {
        for (int i = r + 1; i <= N; ++i) g_row_ptr[i] = E;
    }
}

__global__ __launch_bounds__(256) void spmm_f4_kernel(
    const int* __restrict__ col,
    const float* __restrict__ att,   // (E, 4)
    const float* __restrict__ hfeat, // (N, 32)
    float* __restrict__ out,         // (N, 32)
    int N)
{
    int warp = (blockIdx.x * blockDim.x + threadIdx.x) >> 5;
    int lane = threadIdx.x & 31;
    if (warp >= N) return;

    const int beg = g_row_ptr[warp];
    const int end = g_row_ptr[warp + 1];

    const int g  = lane >> 3;      // edge group 0..3
    const int q  = lane & 7;       // feature quarter 0..7 (features 4q..4q+3)
    const int hd = q >> 1;         // head index for this quarter
    const int nmax = N - 1;

    float4 acc = make_float4(0.f, 0.f, 0.f, 0.f);

    // 8 edges per iteration (2 independent LDG.128s in flight for MLP).
    for (int base = beg; base < end; base += 8) {
        int e0 = base + g;
        int e1 = base + 4 + g;
        bool v0 = (e0 < end);
        bool v1 = (e1 < end);
        int s0 = v0 ? e0 : beg;    // safe address (beg < end inside loop)
        int s1 = v1 ? e1 : beg;

        int c0 = __ldg(&col[s0]);
        int c1 = __ldg(&col[s1]);
        c0 = min(max(c0, 0), nmax);
        c1 = min(max(c1, 0), nmax);

        float a0 = __ldg(&att[s0 * 4 + hd]);
        float a1 = __ldg(&att[s1 * 4 + hd]);
        a0 = v0 ? a0 : 0.f;
        a1 = v1 ? a1 : 0.f;

        float4 h0 = __ldg((const float4*)(hfeat + c0 * 32 + q * 4));
        float4 h1 = __ldg((const float4*)(hfeat + c1 * 32 + q * 4));

        acc.x = fmaf(a0, h0.x, acc.x);
        acc.y = fmaf(a0, h0.y, acc.y);
        acc.z = fmaf(a0, h0.z, acc.z);
        acc.w = fmaf(a0, h0.w, acc.w);
        acc.x = fmaf(a1, h1.x, acc.x);
        acc.y = fmaf(a1, h1.y, acc.y);
        acc.z = fmaf(a1, h1.z, acc.z);
        acc.w = fmaf(a1, h1.w, acc.w);
    }

    // Reduce partial sums across the 4 edge groups (lanes l, l+8, l+16, l+24).
    #pragma unroll
    for (int m = 8; m <= 16; m <<= 1) {
        acc.x += __shfl_xor_sync(0xffffffffu, acc.x, m);
        acc.y += __shfl_xor_sync(0xffffffffu, acc.y, m);
        acc.z += __shfl_xor_sync(0xffffffffu, acc.z, m);
        acc.w += __shfl_xor_sync(0xffffffffu, acc.w, m);
    }

    if (lane < 8) {
        ((float4*)out)[warp * 8 + lane] = acc;  // STG.128, coalesced; zeros for empty rows
    }
}

extern "C" void kernel_launch(void* const* d_in, const int* in_sizes, int n_in,
                              void* d_out, int out_size) {
    const int*   row  = (const int*)  d_in[0];
    const int*   col  = (const int*)  d_in[1];
    const float* att  = (const float*)d_in[2];
    const float* hft  = (const float*)d_in[3];
    float*       out  = (float*)      d_out;

    int E = in_sizes[0];
    int N = in_sizes[3] / 32;  // h is (N, 4, 8)

    {
        int threads = 256;
        int blocks = (E + threads - 1) / threads;
        build_row_ptr_kernel<<<blocks, threads>>>(row, E, N);
    }
    {
        int threads = 256;  // 8 warps per block, one warp per row
        int blocks = (N * 32 + threads - 1) / threads;
        spmm_f4_kernel<<<blocks, threads>>>(col, att, hft, out, N);
    }
}

// round 7
// speedup vs baseline: 1.3261x; 1.1273x over previous
#include <cuda_runtime.h>
#include <cuda_bf16.h>

// MultiHeadSpMM: out[r, h*D+d] = sum_{e: row[e]==r} attention[e,h] * h[col[e],h,d]
// N=100000, E=1600000, H=4, D=8 (H*D == 32). row[] is sorted.
//
// R6 (resubmit after infra failure): group-per-row. Each warp owns 4 rows
//   (group g = lane>>3 -> row 4*warp+g), lane q = lane&7 holds features
//   [4q,4q+4) as a float4. No cross-lane reduction. 4-edge unroll per group
//   -> 4 independent 128B gathers in flight per warp. Uniform loop over
//   warp-max degree, predicated tails.

#define MAX_NODES (1 << 21)

__device__ int g_row_ptr[MAX_NODES + 1];

__global__ void build_row_ptr_kernel(const int* __restrict__ row, int E, int N) {
    int e = blockIdx.x * blockDim.x + threadIdx.x;
    if (e >= E) return;
    int r = row[e];
    if (r < 0) r = 0;
    if (r >= N) r = N - 1;
    int prev;
    if (e == 0) {
        prev = -1;
    } else {
        prev = row[e - 1];
        if (prev < 0) prev = 0;
        if (prev >= N) prev = N - 1;
    }
    for (int i = prev + 1; i <= r; ++i) g_row_ptr[i] = e;
    if (e == E - 1) {
        for (int i = r + 1; i <= N; ++i) g_row_ptr[i] = E;
    }
}

__global__ __launch_bounds__(256) void spmm_group_per_row_kernel(
    const int* __restrict__ col,
    const float* __restrict__ att,   // (E, 4)
    const float* __restrict__ hfeat, // (N, 32)
    float* __restrict__ out,         // (N, 32)
    int N)
{
    int warp = (blockIdx.x * blockDim.x + threadIdx.x) >> 5;
    int lane = threadIdx.x & 31;

    const int g  = lane >> 3;       // group 0..3 -> row
    const int q  = lane & 7;        // feature quarter
    const int hd = q >> 1;          // head for this quarter
    const int r  = warp * 4 + g;
    const bool row_ok = (r < N);
    const int nmax = N - 1;

    int beg = 0, end = 0;
    if (row_ok) {
        beg = g_row_ptr[r];
        end = g_row_ptr[r + 1];
    }
    int deg = end - beg;
    int dmax = __reduce_max_sync(0xffffffffu, deg);

    float4 acc = make_float4(0.f, 0.f, 0.f, 0.f);

    for (int it = 0; it < dmax; it += 4) {
        int e0 = beg + it;
        int e1 = e0 + 1;
        int e2 = e0 + 2;
        int e3 = e0 + 3;
        bool v0 = (it     < deg);
        bool v1 = (it + 1 < deg);
        bool v2 = (it + 2 < deg);
        bool v3 = (it + 3 < deg);
        int s0 = v0 ? e0 : 0;       // edge 0 always a valid address
        int s1 = v1 ? e1 : 0;
        int s2 = v2 ? e2 : 0;
        int s3 = v3 ? e3 : 0;

        int c0 = __ldg(&col[s0]);
        int c1 = __ldg(&col[s1]);
        int c2 = __ldg(&col[s2]);
        int c3 = __ldg(&col[s3]);
        c0 = min(max(c0, 0), nmax);
        c1 = min(max(c1, 0), nmax);
        c2 = min(max(c2, 0), nmax);
        c3 = min(max(c3, 0), nmax);

        float a0 = v0 ? __ldg(&att[s0 * 4 + hd]) : 0.f;
        float a1 = v1 ? __ldg(&att[s1 * 4 + hd]) : 0.f;
        float a2 = v2 ? __ldg(&att[s2 * 4 + hd]) : 0.f;
        float a3 = v3 ? __ldg(&att[s3 * 4 + hd]) : 0.f;

        float4 h0 = __ldg((const float4*)(hfeat + c0 * 32 + q * 4));
        float4 h1 = __ldg((const float4*)(hfeat + c1 * 32 + q * 4));
        float4 h2 = __ldg((const float4*)(hfeat + c2 * 32 + q * 4));
        float4 h3 = __ldg((const float4*)(hfeat + c3 * 32 + q * 4));

        acc.x = fmaf(a0, h0.x, acc.x);
        acc.y = fmaf(a0, h0.y, acc.y);
        acc.z = fmaf(a0, h0.z, acc.z);
        acc.w = fmaf(a0, h0.w, acc.w);
        acc.x = fmaf(a1, h1.x, acc.x);
        acc.y = fmaf(a1, h1.y, acc.y);
        acc.z = fmaf(a1, h1.z, acc.z);
        acc.w = fmaf(a1, h1.w, acc.w);
        acc.x = fmaf(a2, h2.x, acc.x);
        acc.y = fmaf(a2, h2.y, acc.y);
        acc.z = fmaf(a2, h2.z, acc.z);
        acc.w = fmaf(a2, h2.w, acc.w);
        acc.x = fmaf(a3, h3.x, acc.x);
        acc.y = fmaf(a3, h3.y, acc.y);
        acc.z = fmaf(a3, h3.z, acc.z);
        acc.w = fmaf(a3, h3.w, acc.w);
    }

    if (row_ok) {
        // Warp stores 4 rows * 32 floats = 512B contiguous; zeros for empty rows.
        ((float4*)out)[r * 8 + q] = acc;
    }
}

extern "C" void kernel_launch(void* const* d_in, const int* in_sizes, int n_in,
                              void* d_out, int out_size) {
    const int*   row  = (const int*)  d_in[0];
    const int*   col  = (const int*)  d_in[1];
    const float* att  = (const float*)d_in[2];
    const float* hft  = (const float*)d_in[3];
    float*       out  = (float*)      d_out;

    int E = in_sizes[0];
    int N = in_sizes[3] / 32;  // h is (N, 4, 8)

    {
        int threads = 256;
        int blocks = (E + threads - 1) / threads;
        build_row_ptr_kernel<<<blocks, threads>>>(row, E, N);
    }
    {
        int threads = 256;                     // 8 warps = 32 rows per block
        int rows_per_block = (threads / 32) * 4;
        int blocks = (N + rows_per_block - 1) / rows_per_block;
        spmm_group_per_row_kernel<<<blocks, threads>>>(col, att, hft, out, N);
    }
}